// round 15
// baseline (speedup 1.0000x reference)
#include <cuda_runtime.h>
#include <cuda.h>
#include <cuda_bf16.h>
#include <cstdint>

#define N_PTS 6000
#define N_TRI 16000
#define N_MOV 4000
#define N_BND 1500
#define BATCH 16
#define EPSF 1e-8f

// GEMM: C[m=4000,n=16] = Vf[m,k=16000] * D[k,16]
#define CK 64
#define NCHUNK (N_TRI / CK)    // 250
#define KS 9
#define MTILES 32
#define NST 3                  // pass-1 stages (f32 A)

#define A_HALF 16384
#define A_STAGE (2 * A_HALF)                 // 32768
#define B_STAGE 4096
#define STAGE_SZ (A_STAGE + B_STAGE)         // 36864
#define SMEM_BYTES (NST * STAGE_SZ)          // 110592 -> 2 CTAs/SM (measured)
#define STAGE_TX STAGE_SZ

// pass-2/3: bf16 A plane, CK2=128, 2-stage
#define CK2 128
#define NCHUNK2 (N_TRI / CK2)                // 125
#define A2_HALF 16384
#define A2_STAGE (2 * A2_HALF)               // 32768
#define B2_HALF 4096
#define B2_STAGE (2 * B2_HALF)               // 8192
#define STAGE2_SZ (A2_STAGE + B2_STAGE)      // 40960
#define NST2 2
#define SMEM2_BYTES (NST2 * STAGE2_SZ)       // 81920 -> 2 CTAs/SM
#define STAGE2_TX STAGE2_SZ

#define VOLBLK 63

// PDL intrinsics (PTX griddepcontrol, sm_90+ baseline)
__device__ __forceinline__ void gdep_wait() { asm volatile("griddepcontrol.wait;" ::: "memory"); }
__device__ __forceinline__ void gdep_trig() { asm volatile("griddepcontrol.launch_dependents;" ::: "memory"); }

// ------------------------- device scratch -------------------------
__device__ int    g_owner[2 * N_PTS];
__device__ double g_volpart[(BATCH + 1) * VOLBLK];
__device__ float  g_pz[BATCH * N_PTS * 3];
__device__ __align__(256) __nv_bfloat16 g_dsp[32 * N_TRI];   // rows 0-15 hi[b], 16-31 lo[b]
__device__ __align__(256) __nv_bfloat16 g_vfh[(size_t)4096 * N_TRI];  // Vf hi-plane
__device__ float  g_cpart[KS * 4096 * 16];
__device__ float  g_c[BATCH * N_MOV];

// ------------------------- small kernels -------------------------
__global__ void k_owners(const int* __restrict__ idx1, const int* __restrict__ idx2) {
    gdep_wait();
    int i = blockIdx.x * 256 + threadIdx.x;
    if (i < N_MOV) atomicMax(&g_owner[idx1[i]], i);
    if (i < N_BND) atomicMax(&g_owner[N_PTS + idx2[i]], i);
    gdep_trig();
}

__global__ void k_build(const float* __restrict__ x, const float* __restrict__ y,
                        const float* __restrict__ pz0) {
    gdep_wait();
    int i = blockIdx.x * 256 + threadIdx.x;
    if (i < BATCH * N_PTS) {
        int b = i / N_PTS, p = i - b * N_PTS;
        float cx = pz0[p * 3 + 0], cy = pz0[p * 3 + 1], cz = pz0[p * 3 + 2];
        int o2 = g_owner[N_PTS + p];
        if (o2 >= 0) {
            cx = y[b * (2 * N_BND) + o2 * 2 + 0];
            cz = y[b * (2 * N_BND) + o2 * 2 + 1];
        }
        int o1 = g_owner[p];
        if (o1 >= 0) {
            cx = x[(b * N_MOV + o1) * 3 + 0];
            cy = x[(b * N_MOV + o1) * 3 + 1];
            cz = x[(b * N_MOV + o1) * 3 + 2];
        }
        g_pz[i * 3 + 0] = cx; g_pz[i * 3 + 1] = cy; g_pz[i * 3 + 2] = cz;
    }
    gdep_trig();
}

__global__ void k_vol(const float* __restrict__ pz0, const int* __restrict__ tri) {
    __shared__ double sred[256];
    int t = blockIdx.x * 256 + threadIdx.x;
    int b = blockIdx.y;
    const float* P = (b < BATCH) ? (g_pz + (size_t)b * N_PTS * 3) : pz0;
    double contrib = 0.0;
    if (t < N_TRI) {
        int p0 = tri[3 * t + 0] * 3, p1 = tri[3 * t + 1] * 3, p2 = tri[3 * t + 2] * 3;
        float x0 = P[p0], y0 = P[p0 + 1], z0 = P[p0 + 2];
        float x1 = P[p1], y1 = P[p1 + 1], z1 = P[p1 + 2];
        float x2 = P[p2], y2 = P[p2 + 1], z2 = P[p2 + 2];
        float det = (y1 - y0) * (z2 - z0) - (z1 - z0) * (y2 - y0);
        contrib = (double)((x0 + x1 + x2) * (det * (1.0f / 6.0f)));
    }
    sred[threadIdx.x] = contrib;
    __syncthreads();
    for (int o = 128; o > 0; o >>= 1) {
        if (threadIdx.x < o) sred[threadIdx.x] += sred[threadIdx.x + o];
        __syncthreads();
    }
    if (threadIdx.x == 0) g_volpart[b * VOLBLK + blockIdx.x] = sred[0];
}

template <int AXIS>
__global__ void k_det(const int* __restrict__ tri) {
    gdep_wait();
    int t = blockIdx.x * 256 + threadIdx.x;
    if (t < N_TRI) {
        const int p0 = tri[3 * t + 0] * 3, p1 = tri[3 * t + 1] * 3, p2 = tri[3 * t + 2] * 3;
        const int b0 = blockIdx.y * 4;
#pragma unroll
        for (int bi = 0; bi < 4; bi++) {
            const int b = b0 + bi;
            const float* P = g_pz + (size_t)b * N_PTS * 3;
            float det;
            if (AXIS == 2) {
                float x0 = P[p0], y0 = P[p0 + 1], x1 = P[p1], y1 = P[p1 + 1], x2 = P[p2], y2 = P[p2 + 1];
                det = (x0 - x2) * (y1 - y2) - (y0 - y2) * (x1 - x2);
            } else if (AXIS == 1) {
                float x0 = P[p0], z0 = P[p0 + 2], x1 = P[p1], z1 = P[p1 + 2], x2 = P[p2], z2 = P[p2 + 2];
                det = (x0 - x1) * (z2 - z1) - (z0 - z1) * (x2 - x1);
            } else {
                float y0 = P[p0 + 1], z0 = P[p0 + 2], y1 = P[p1 + 1], z1 = P[p1 + 2], y2 = P[p2 + 1], z2 = P[p2 + 2];
                det = (y1 - y0) * (z2 - z0) - (z1 - z0) * (y2 - y0);
            }
            float v = det * (1.0f / 6.0f);
            __nv_bfloat16 h = __float2bfloat16_rn(v);
            __nv_bfloat16 l = __float2bfloat16_rn(v - __bfloat162float(h));
            g_dsp[b * N_TRI + t] = h;
            g_dsp[(16 + b) * N_TRI + t] = l;
        }
    }
    gdep_trig();
}

// ------------------------- helpers -------------------------
__device__ __forceinline__ uint32_t smem_u32(const void* p) {
    return (uint32_t)__cvta_generic_to_shared(p);
}
__device__ __forceinline__ void tma2d(uint32_t dst, const CUtensorMap* m, int x, int y, uint32_t mbar) {
    asm volatile(
        "cp.async.bulk.tensor.2d.shared::cta.global.tile.mbarrier::complete_tx::bytes "
        "[%0], [%1, {%2, %3}], [%4];"
        :: "r"(dst), "l"(m), "r"(x), "r"(y), "r"(mbar) : "memory");
}
__device__ __forceinline__ void mbar_wait(uint32_t addr, uint32_t parity) {
    asm volatile(
        "{\n\t.reg .pred P;\n\t"
        "W%=:\n\tmbarrier.try_wait.parity.acquire.cta.shared::cta.b64 P, [%0], %1;\n\t"
        "@!P bra W%=;\n\t}"
        :: "r"(addr), "r"(parity) : "memory");
}
__device__ __forceinline__ uint32_t bhi(float a0, float a1) {
    uint32_t h;
    asm("cvt.rn.bf16x2.f32 %0, %1, %2;" : "=r"(h) : "f"(a1), "f"(a0));
    return h;
}
#define MMA16816(C0,C1,C2,C3,A0,A1,A2,A3,B0,B1) \
    asm("mma.sync.aligned.m16n8k16.row.col.f32.bf16.bf16.f32 " \
        "{%0,%1,%2,%3},{%4,%5,%6,%7},{%8,%9},{%0,%1,%2,%3};" \
        : "+f"(C0), "+f"(C1), "+f"(C2), "+f"(C3) \
        : "r"(A0), "r"(A1), "r"(A2), "r"(A3), "r"(B0), "r"(B1))

// ------------------------- GEMM pass 1: f32 Vf in, writes coalesced bf16 hi-plane -------------------------
__global__ void __launch_bounds__(256) k_gemm1(const __grid_constant__ CUtensorMap tmA,
                                               const __grid_constant__ CUtensorMap tmB) {
    extern __shared__ __align__(1024) char sm[];
    __shared__ __align__(8) unsigned long long s_mbar[NST];

    const int tid  = threadIdx.x;
    const int lane = tid & 31;
    const int w    = tid >> 5;
    const int g    = lane >> 2;
    const int tig  = lane & 3;
    const int mbase = blockIdx.x * 128;
    const int ksid  = blockIdx.y;
    const int c0 = (NCHUNK * ksid) / KS;
    const int c1 = (NCHUNK * (ksid + 1)) / KS;

    uint32_t mb[NST];
#pragma unroll
    for (int s = 0; s < NST; s++) mb[s] = smem_u32(&s_mbar[s]);
    if (tid == 0) {
#pragma unroll
        for (int s = 0; s < NST; s++)
            asm volatile("mbarrier.init.shared.b64 [%0], 1;" :: "r"(mb[s]) : "memory");
        asm volatile("fence.proxy.async.shared::cta;" ::: "memory");
    }
    gdep_wait();          // dsp must be complete before TMA B loads
    __syncthreads();

    const uint32_t sbase = smem_u32(sm);

    auto issue = [&](int st, int it) {
        if (tid == 0) {
            const int t0 = it * CK;
            asm volatile("mbarrier.arrive.expect_tx.shared.b64 _, [%0], %1;"
                         :: "r"(mb[st]), "r"((uint32_t)STAGE_TX) : "memory");
            tma2d(sbase + st * STAGE_SZ,           &tmA, t0,      mbase, mb[st]);
            tma2d(sbase + st * STAGE_SZ + A_HALF,  &tmA, t0 + 32, mbase, mb[st]);
            tma2d(sbase + st * STAGE_SZ + A_STAGE, &tmB, t0,      0,     mb[st]);
        }
    };

    const int niter = c1 - c0;
#pragma unroll
    for (int s = 0; s < NST; s++)
        if (s < niter) issue(s, c0 + s);

    gdep_trig();          // dependent su is tiny; let it pre-launch and spin

    float acc[2][4];
#pragma unroll
    for (int nt = 0; nt < 2; nt++)
#pragma unroll
        for (int q = 0; q < 4; q++) acc[nt][q] = 0.f;

    int phase[NST] = { 0, 0, 0 };
    int st = 0;
    const int swz = g << 4;

    const int seg   = tid & 7;
    const int rbase = tid >> 3;
    const int segoff = (seg & 3) * 32;

    for (int li = 0; li < niter; ++li) {
        mbar_wait(mb[st], phase[st]);
        phase[st] ^= 1;

        const char* S = sm + st * STAGE_SZ;
        const char* Brow = S + A_STAGE + g * 128;
        const int tglob = (c0 + li) * CK;

        // coalesced hi-plane store (row-contiguous, STG.128)
        {
            const char* Af = S + (seg >> 2) * A_HALF;
#pragma unroll
            for (int j = 0; j < 4; j++) {
                const int r = rbase + 32 * j;
                const int rswz = (r & 7) << 4;
                const char* p = Af + r * 128;
                float4 f0 = *reinterpret_cast<const float4*>(p + (segoff ^ rswz));
                float4 f1 = *reinterpret_cast<const float4*>(p + ((segoff + 16) ^ rswz));
                uint4 o;
                o.x = bhi(f0.x, f0.y); o.y = bhi(f0.z, f0.w);
                o.z = bhi(f1.x, f1.y); o.w = bhi(f1.z, f1.w);
                *reinterpret_cast<uint4*>(
                    (char*)g_vfh + ((size_t)(mbase + r) * N_TRI + tglob) * 2 + seg * 16) = o;
            }
        }

#pragma unroll
        for (int ks = 0; ks < 4; ks++) {
            const char* Ah = S + (ks >> 1) * A_HALF + (w * 16 + g) * 128;
            const int cb = (ks & 1) * 64 + tig * 8;
            float2 x00 = *reinterpret_cast<const float2*>(Ah + ((cb)      ^ swz));
            float2 x01 = *reinterpret_cast<const float2*>(Ah + ((cb + 32) ^ swz));
            float2 x10 = *reinterpret_cast<const float2*>(Ah + 1024 + ((cb)      ^ swz));
            float2 x11 = *reinterpret_cast<const float2*>(Ah + 1024 + ((cb + 32) ^ swz));
            uint32_t ah0 = bhi(x00.x, x00.y);
            uint32_t ah1 = bhi(x10.x, x10.y);
            uint32_t ah2 = bhi(x01.x, x01.y);
            uint32_t ah3 = bhi(x11.x, x11.y);

            const int kb = ks * 32 + tig * 4;
            uint32_t bh0a = *reinterpret_cast<const uint32_t*>(Brow + ((kb)      ^ swz));
            uint32_t bh0b = *reinterpret_cast<const uint32_t*>(Brow + ((kb + 16) ^ swz));
            uint32_t bh1a = *reinterpret_cast<const uint32_t*>(Brow + 8 * 128  + ((kb)      ^ swz));
            uint32_t bh1b = *reinterpret_cast<const uint32_t*>(Brow + 8 * 128  + ((kb + 16) ^ swz));
            uint32_t bl0a = *reinterpret_cast<const uint32_t*>(Brow + 16 * 128 + ((kb)      ^ swz));
            uint32_t bl0b = *reinterpret_cast<const uint32_t*>(Brow + 16 * 128 + ((kb + 16) ^ swz));
            uint32_t bl1a = *reinterpret_cast<const uint32_t*>(Brow + 24 * 128 + ((kb)      ^ swz));
            uint32_t bl1b = *reinterpret_cast<const uint32_t*>(Brow + 24 * 128 + ((kb + 16) ^ swz));

            MMA16816(acc[0][0], acc[0][1], acc[0][2], acc[0][3], ah0, ah1, ah2, ah3, bh0a, bh0b);
            MMA16816(acc[0][0], acc[0][1], acc[0][2], acc[0][3], ah0, ah1, ah2, ah3, bl0a, bl0b);
            MMA16816(acc[1][0], acc[1][1], acc[1][2], acc[1][3], ah0, ah1, ah2, ah3, bh1a, bh1b);
            MMA16816(acc[1][0], acc[1][1], acc[1][2], acc[1][3], ah0, ah1, ah2, ah3, bl1a, bl1b);
        }

        __syncthreads();
        if (li + NST < niter) issue(st, c0 + li + NST);
        st = (st + 1 == NST) ? 0 : st + 1;
    }

    const int m0 = mbase + w * 16 + g;
    const int m1 = m0 + 8;
#pragma unroll
    for (int nt = 0; nt < 2; nt++) {
        const int n0 = nt * 8 + tig * 2;
        if (m0 < N_MOV)
            *reinterpret_cast<float2*>(&g_cpart[((size_t)ksid * 4096 + m0) * 16 + n0]) =
                make_float2(acc[nt][0], acc[nt][1]);
        if (m1 < N_MOV)
            *reinterpret_cast<float2*>(&g_cpart[((size_t)ksid * 4096 + m1) * 16 + n0]) =
                make_float2(acc[nt][2], acc[nt][3]);
    }
}

// ------------------------- GEMM pass 2/3: bf16 hi-plane, CK2=128, 2-stage -------------------------
__global__ void __launch_bounds__(256) k_gemm2(const __grid_constant__ CUtensorMap tmH,
                                               const __grid_constant__ CUtensorMap tmB) {
    extern __shared__ __align__(1024) char sm[];
    __shared__ __align__(8) unsigned long long s_mbar[NST2];

    const int tid  = threadIdx.x;
    const int lane = tid & 31;
    const int w    = tid >> 5;
    const int g    = lane >> 2;
    const int tig  = lane & 3;
    const int mbase = blockIdx.x * 128;
    const int ksid  = blockIdx.y;
    const int c0 = (NCHUNK2 * ksid) / KS;
    const int c1 = (NCHUNK2 * (ksid + 1)) / KS;

    uint32_t mb[NST2];
#pragma unroll
    for (int s = 0; s < NST2; s++) mb[s] = smem_u32(&s_mbar[s]);
    if (tid == 0) {
#pragma unroll
        for (int s = 0; s < NST2; s++)
            asm volatile("mbarrier.init.shared.b64 [%0], 1;" :: "r"(mb[s]) : "memory");
        asm volatile("fence.proxy.async.shared::cta;" ::: "memory");
    }
    gdep_wait();          // dsp from det must be complete
    __syncthreads();

    const uint32_t sbase = smem_u32(sm);

    auto issue = [&](int st, int it) {
        if (tid == 0) {
            const int t0 = it * CK2;
            asm volatile("mbarrier.arrive.expect_tx.shared.b64 _, [%0], %1;"
                         :: "r"(mb[st]), "r"((uint32_t)STAGE2_TX) : "memory");
            tma2d(sbase + st * STAGE2_SZ,                       &tmH, t0,      mbase, mb[st]);
            tma2d(sbase + st * STAGE2_SZ + A2_HALF,             &tmH, t0 + 64, mbase, mb[st]);
            tma2d(sbase + st * STAGE2_SZ + A2_STAGE,            &tmB, t0,      0,     mb[st]);
            tma2d(sbase + st * STAGE2_SZ + A2_STAGE + B2_HALF,  &tmB, t0 + 64, 0,     mb[st]);
        }
    };

    const int niter = c1 - c0;
#pragma unroll
    for (int s = 0; s < NST2; s++)
        if (s < niter) issue(s, c0 + s);

    gdep_trig();

    float acc[2][4];
#pragma unroll
    for (int nt = 0; nt < 2; nt++)
#pragma unroll
        for (int q = 0; q < 4; q++) acc[nt][q] = 0.f;

    int phase[NST2] = { 0, 0 };
    int st = 0;
    const int swz = g << 4;

    for (int li = 0; li < niter; ++li) {
        mbar_wait(mb[st], phase[st]);
        phase[st] ^= 1;

        const char* S = sm + st * STAGE2_SZ;

#pragma unroll
        for (int half = 0; half < 2; half++) {
            const char* Arow = S + half * A2_HALF + (w * 16 + g) * 128;
            const char* Brow = S + A2_STAGE + half * B2_HALF + g * 128;
#pragma unroll
            for (int ks = 0; ks < 4; ks++) {
                const int kb = ks * 32 + tig * 4;
                uint32_t ah0 = *reinterpret_cast<const uint32_t*>(Arow + ((kb)      ^ swz));
                uint32_t ah2 = *reinterpret_cast<const uint32_t*>(Arow + ((kb + 16) ^ swz));
                uint32_t ah1 = *reinterpret_cast<const uint32_t*>(Arow + 8 * 128 + ((kb)      ^ swz));
                uint32_t ah3 = *reinterpret_cast<const uint32_t*>(Arow + 8 * 128 + ((kb + 16) ^ swz));

                uint32_t bh0a = *reinterpret_cast<const uint32_t*>(Brow + ((kb)      ^ swz));
                uint32_t bh0b = *reinterpret_cast<const uint32_t*>(Brow + ((kb + 16) ^ swz));
                uint32_t bh1a = *reinterpret_cast<const uint32_t*>(Brow + 8 * 128  + ((kb)      ^ swz));
                uint32_t bh1b = *reinterpret_cast<const uint32_t*>(Brow + 8 * 128  + ((kb + 16) ^ swz));
                uint32_t bl0a = *reinterpret_cast<const uint32_t*>(Brow + 16 * 128 + ((kb)      ^ swz));
                uint32_t bl0b = *reinterpret_cast<const uint32_t*>(Brow + 16 * 128 + ((kb + 16) ^ swz));
                uint32_t bl1a = *reinterpret_cast<const uint32_t*>(Brow + 24 * 128 + ((kb)      ^ swz));
                uint32_t bl1b = *reinterpret_cast<const uint32_t*>(Brow + 24 * 128 + ((kb + 16) ^ swz));

                MMA16816(acc[0][0], acc[0][1], acc[0][2], acc[0][3], ah0, ah1, ah2, ah3, bh0a, bh0b);
                MMA16816(acc[0][0], acc[0][1], acc[0][2], acc[0][3], ah0, ah1, ah2, ah3, bl0a, bl0b);
                MMA16816(acc[1][0], acc[1][1], acc[1][2], acc[1][3], ah0, ah1, ah2, ah3, bh1a, bh1b);
                MMA16816(acc[1][0], acc[1][1], acc[1][2], acc[1][3], ah0, ah1, ah2, ah3, bl1a, bl1b);
            }
        }

        __syncthreads();
        if (li + NST2 < niter) issue(st, c0 + li + NST2);
        st = (st + 1 == NST2) ? 0 : st + 1;
    }

    const int m0 = mbase + w * 16 + g;
    const int m1 = m0 + 8;
#pragma unroll
    for (int nt = 0; nt < 2; nt++) {
        const int n0 = nt * 8 + tig * 2;
        if (m0 < N_MOV)
            *reinterpret_cast<float2*>(&g_cpart[((size_t)ksid * 4096 + m0) * 16 + n0]) =
                make_float2(acc[nt][0], acc[nt][1]);
        if (m1 < N_MOV)
            *reinterpret_cast<float2*>(&g_cpart[((size_t)ksid * 4096 + m1) * 16 + n0]) =
                make_float2(acc[nt][2], acc[nt][3]);
    }
}

// ------------------------- fused: finalize c, vol reduce, scale, update out & pz -------------------------
__global__ void k_scale_update(const int* __restrict__ idx1, const float* __restrict__ x,
                               float* __restrict__ out, int axis) {
    __shared__ float red[256];
    __shared__ double dv[128];
    __shared__ float s_scale;
    int b = blockIdx.x;
    int tid = threadIdx.x;

    gdep_wait();

    if (tid < 128) {
        double v = 0.0;
        if (tid < 64) { if (tid < VOLBLK) v = g_volpart[b * VOLBLK + tid]; }
        else          { if (tid - 64 < VOLBLK) v = g_volpart[BATCH * VOLBLK + (tid - 64)]; }
        dv[tid] = v;
    }

    float sq = 0.f;
    for (int m = tid; m < N_MOV; m += 256) {
        float cv = 0.f;
#pragma unroll
        for (int sp = 0; sp < KS; sp++)
            cv += g_cpart[((size_t)sp * 4096 + m) * 16 + b];
        g_c[b * N_MOV + m] = cv;
        sq += cv * cv;
    }
    red[tid] = sq;
    __syncthreads();
    for (int o = 32; o > 0; o >>= 1) {
        if (tid < o)                   dv[tid] += dv[tid + o];
        if (tid >= 64 && tid < 64 + o) dv[tid] += dv[tid + o];
        __syncthreads();
    }
    for (int o = 128; o > 0; o >>= 1) {
        if (tid < o) red[tid] += red[tid + o];
        __syncthreads();
    }
    if (tid == 0) {
        float a = (float)((dv[64] - dv[0]) / 3.0);
        s_scale = a / (red[0] + EPSF);
    }
    __syncthreads();
    const float s = s_scale;
    for (int m = tid; m < N_MOV; m += 256) {
        int i = b * N_MOV + m;
        float nv = x[i * 3 + axis] + g_c[i] * s;
        out[i * 3 + axis] = nv;
        int p = idx1[m];
        if (g_owner[p] == m) g_pz[((size_t)b * N_PTS + p) * 3 + axis] = nv;
    }
    gdep_trig();
}

// ------------------------- host -------------------------
typedef CUresult (*EncodeFn)(CUtensorMap*, CUtensorMapDataType, cuuint32_t, void*,
                             const cuuint64_t*, const cuuint64_t*, const cuuint32_t*,
                             const cuuint32_t*, CUtensorMapInterleave, CUtensorMapSwizzle,
                             CUtensorMapL2promotion, CUtensorMapFloatOOBfill);

template <typename F, typename... Args>
static void launch_pdl(F kern, dim3 grid, dim3 block, size_t smem, Args... args) {
    cudaLaunchConfig_t cfg = {};
    cfg.gridDim = grid;
    cfg.blockDim = block;
    cfg.dynamicSmemBytes = smem;
    cfg.stream = 0;
    cudaLaunchAttribute attr[1];
    attr[0].id = cudaLaunchAttributeProgrammaticStreamSerialization;
    attr[0].val.programmaticStreamSerializationAllowed = 1;
    cfg.attrs = attr;
    cfg.numAttrs = 1;
    cudaLaunchKernelEx(&cfg, kern, args...);
}

extern "C" void kernel_launch(void* const* d_in, const int* in_sizes, int n_in,
                              void* d_out, int out_size) {
    const float* x   = (const float*)d_in[0];
    const float* y   = (const float*)d_in[1];
    const float* pz0 = (const float*)d_in[2];
    const float* Vf  = (const float*)d_in[3];
    const int* idx1  = (const int*)d_in[4];
    const int* idx2  = (const int*)d_in[5];
    const int* tri   = (const int*)d_in[6];
    float* out = (float*)d_out;

    cudaFuncSetAttribute(k_gemm1, cudaFuncAttributeMaxDynamicSharedMemorySize, SMEM_BYTES);
    cudaFuncSetAttribute(k_gemm2, cudaFuncAttributeMaxDynamicSharedMemorySize, SMEM2_BYTES);

    EncodeFn enc = nullptr;
    {
        void* p = nullptr;
        cudaDriverEntryPointQueryResult qr;
        cudaGetDriverEntryPoint("cuTensorMapEncodeTiled", &p, cudaEnableDefault, &qr);
        enc = (EncodeFn)p;
    }

    void* dsp_ptr = nullptr;
    cudaGetSymbolAddress(&dsp_ptr, g_dsp);
    void* vfh_ptr = nullptr;
    cudaGetSymbolAddress(&vfh_ptr, g_vfh);

    CUtensorMap tmA, tmB, tmH;
    {
        cuuint64_t dims[2]    = { (cuuint64_t)N_TRI, (cuuint64_t)N_MOV };
        cuuint64_t strides[1] = { (cuuint64_t)N_TRI * 4 };
        cuuint32_t box[2]     = { 32, 128 };
        cuuint32_t es[2]      = { 1, 1 };
        enc(&tmA, CU_TENSOR_MAP_DATA_TYPE_FLOAT32, 2, (void*)Vf,
            dims, strides, box, es,
            CU_TENSOR_MAP_INTERLEAVE_NONE, CU_TENSOR_MAP_SWIZZLE_128B,
            CU_TENSOR_MAP_L2_PROMOTION_L2_128B, CU_TENSOR_MAP_FLOAT_OOB_FILL_NONE);
    }
    {
        cuuint64_t dims[2]    = { (cuuint64_t)N_TRI, 32 };
        cuuint64_t strides[1] = { (cuuint64_t)N_TRI * 2 };
        cuuint32_t box[2]     = { 64, 32 };
        cuuint32_t es[2]      = { 1, 1 };
        enc(&tmB, CU_TENSOR_MAP_DATA_TYPE_BFLOAT16, 2, dsp_ptr,
            dims, strides, box, es,
            CU_TENSOR_MAP_INTERLEAVE_NONE, CU_TENSOR_MAP_SWIZZLE_128B,
            CU_TENSOR_MAP_L2_PROMOTION_L2_128B, CU_TENSOR_MAP_FLOAT_OOB_FILL_NONE);
    }
    {
        cuuint64_t dims[2]    = { (cuuint64_t)N_TRI, 4096 };
        cuuint64_t strides[1] = { (cuuint64_t)N_TRI * 2 };
        cuuint32_t box[2]     = { 64, 128 };
        cuuint32_t es[2]      = { 1, 1 };
        enc(&tmH, CU_TENSOR_MAP_DATA_TYPE_BFLOAT16, 2, vfh_ptr,
            dims, strides, box, es,
            CU_TENSOR_MAP_INTERLEAVE_NONE, CU_TENSOR_MAP_SWIZZLE_128B,
            CU_TENSOR_MAP_L2_PROMOTION_L2_128B, CU_TENSOR_MAP_FLOAT_OOB_FILL_NONE);
    }

    static cudaStream_t s2 = nullptr;
    static cudaEvent_t evA = nullptr, evB = nullptr;
    if (!s2) {
        cudaStreamCreateWithFlags(&s2, cudaStreamNonBlocking);
        cudaEventCreateWithFlags(&evA, cudaEventDisableTiming);
        cudaEventCreateWithFlags(&evB, cudaEventDisableTiming);
    }

    void* op = nullptr;
    cudaGetSymbolAddress(&op, g_owner);
    cudaMemsetAsync(op, 0xFF, 2 * N_PTS * sizeof(int));

    launch_pdl(k_owners, dim3(16), dim3(256), 0, idx1, idx2);
    launch_pdl(k_build, dim3(375), dim3(256), 0, x, y, pz0);

    // fork: k_vol depends only on k_build; runs concurrent with det2/gemm1
    cudaEventRecord(evA, 0);
    cudaStreamWaitEvent(s2, evA, 0);
    k_vol<<<dim3(VOLBLK, BATCH + 1), 256, 0, s2>>>(pz0, tri);
    cudaEventRecord(evB, s2);

    launch_pdl(k_det<2>, dim3(63, 4), dim3(256), 0, tri);
    launch_pdl(k_gemm1, dim3(MTILES, KS), dim3(256), (size_t)SMEM_BYTES, tmA, tmB);
    cudaStreamWaitEvent(0, evB, 0);
    launch_pdl(k_scale_update, dim3(BATCH), dim3(256), 0, idx1, x, out, 2);

    launch_pdl(k_det<1>, dim3(63, 4), dim3(256), 0, tri);
    launch_pdl(k_gemm2, dim3(MTILES, KS), dim3(256), (size_t)SMEM2_BYTES, tmH, tmB);
    launch_pdl(k_scale_update, dim3(BATCH), dim3(256), 0, idx1, x, out, 1);

    launch_pdl(k_det<0>, dim3(63, 4), dim3(256), 0, tri);
    launch_pdl(k_gemm2, dim3(MTILES, KS), dim3(256), (size_t)SMEM2_BYTES, tmH, tmB);
    launch_pdl(k_scale_update, dim3(BATCH), dim3(256), 0, idx1, x, out, 0);
}

// round 16
// speedup vs baseline: 1.2817x; 1.2817x over previous
#include <cuda_runtime.h>
#include <cuda.h>
#include <cuda_bf16.h>
#include <cstdint>

#define N_PTS 6000
#define N_TRI 16000
#define N_MOV 4000
#define N_BND 1500
#define BATCH 16
#define EPSF 1e-8f

// GEMM: C[m=4000,n=16] = Vf[m,k=16000] * D[k,16]
#define CK 64
#define NCHUNK (N_TRI / CK)    // 250
#define KS 9
#define MTILES 32
#define NST 3                  // pass-1 stages (f32 A)

#define A_HALF 16384
#define A_STAGE (2 * A_HALF)                 // 32768
#define B_STAGE 4096
#define STAGE_SZ (A_STAGE + B_STAGE)         // 36864
#define SMEM_BYTES (NST * STAGE_SZ)          // 110592 -> 2 CTAs/SM (measured)
#define STAGE_TX STAGE_SZ

// pass-2/3: bf16 A plane, CK2=128, 2-stage
#define CK2 128
#define NCHUNK2 (N_TRI / CK2)                // 125
#define A2_HALF 16384
#define A2_STAGE (2 * A2_HALF)               // 32768
#define B2_HALF 4096
#define B2_STAGE (2 * B2_HALF)               // 8192
#define STAGE2_SZ (A2_STAGE + B2_STAGE)      // 40960
#define NST2 2
#define SMEM2_BYTES (NST2 * STAGE2_SZ)       // 81920 -> 2 CTAs/SM
#define STAGE2_TX STAGE2_SZ

#define VOLBLK 63

// ------------------------- device scratch -------------------------
__device__ int    g_owner[2 * N_PTS];
__device__ double g_volpart[(BATCH + 1) * VOLBLK];
__device__ float  g_pz[BATCH * N_PTS * 3];
__device__ __align__(256) __nv_bfloat16 g_dsp[32 * N_TRI];   // rows 0-15 hi[b], 16-31 lo[b]
__device__ __align__(256) __nv_bfloat16 g_vfh[(size_t)4096 * N_TRI];  // Vf hi-plane
__device__ float  g_cpart[KS * 4096 * 16];
__device__ float  g_c[BATCH * N_MOV];

// ------------------------- small kernels -------------------------
__global__ void k_owners(const int* __restrict__ idx1, const int* __restrict__ idx2) {
    int i = blockIdx.x * 256 + threadIdx.x;
    if (i < N_MOV) atomicMax(&g_owner[idx1[i]], i);
    if (i < N_BND) atomicMax(&g_owner[N_PTS + idx2[i]], i);
}

__global__ void k_build(const float* __restrict__ x, const float* __restrict__ y,
                        const float* __restrict__ pz0) {
    int i = blockIdx.x * 256 + threadIdx.x;
    if (i >= BATCH * N_PTS) return;
    int b = i / N_PTS, p = i - b * N_PTS;
    float cx = pz0[p * 3 + 0], cy = pz0[p * 3 + 1], cz = pz0[p * 3 + 2];
    int o2 = g_owner[N_PTS + p];
    if (o2 >= 0) {
        cx = y[b * (2 * N_BND) + o2 * 2 + 0];
        cz = y[b * (2 * N_BND) + o2 * 2 + 1];
    }
    int o1 = g_owner[p];
    if (o1 >= 0) {
        cx = x[(b * N_MOV + o1) * 3 + 0];
        cy = x[(b * N_MOV + o1) * 3 + 1];
        cz = x[(b * N_MOV + o1) * 3 + 2];
    }
    g_pz[i * 3 + 0] = cx; g_pz[i * 3 + 1] = cy; g_pz[i * 3 + 2] = cz;
}

__global__ void k_vol(const float* __restrict__ pz0, const int* __restrict__ tri) {
    __shared__ double sred[256];
    int t = blockIdx.x * 256 + threadIdx.x;
    int b = blockIdx.y;
    const float* P = (b < BATCH) ? (g_pz + (size_t)b * N_PTS * 3) : pz0;
    double contrib = 0.0;
    if (t < N_TRI) {
        int p0 = tri[3 * t + 0] * 3, p1 = tri[3 * t + 1] * 3, p2 = tri[3 * t + 2] * 3;
        float x0 = P[p0], y0 = P[p0 + 1], z0 = P[p0 + 2];
        float x1 = P[p1], y1 = P[p1 + 1], z1 = P[p1 + 2];
        float x2 = P[p2], y2 = P[p2 + 1], z2 = P[p2 + 2];
        float det = (y1 - y0) * (z2 - z0) - (z1 - z0) * (y2 - y0);
        contrib = (double)((x0 + x1 + x2) * (det * (1.0f / 6.0f)));
    }
    sred[threadIdx.x] = contrib;
    __syncthreads();
    for (int o = 128; o > 0; o >>= 1) {
        if (threadIdx.x < o) sred[threadIdx.x] += sred[threadIdx.x + o];
        __syncthreads();
    }
    if (threadIdx.x == 0) g_volpart[b * VOLBLK + blockIdx.x] = sred[0];
}

// dets -> bf16 hi/lo planes; grid (63, 8): thread owns t, 2 batches (504 blocks -> ~42% occ)
template <int AXIS>
__global__ void k_det(const int* __restrict__ tri) {
    int t = blockIdx.x * 256 + threadIdx.x;
    if (t >= N_TRI) return;
    const int p0 = tri[3 * t + 0] * 3, p1 = tri[3 * t + 1] * 3, p2 = tri[3 * t + 2] * 3;
    const int b0 = blockIdx.y * 2;
#pragma unroll
    for (int bi = 0; bi < 2; bi++) {
        const int b = b0 + bi;
        const float* P = g_pz + (size_t)b * N_PTS * 3;
        float det;
        if (AXIS == 2) {
            float x0 = P[p0], y0 = P[p0 + 1], x1 = P[p1], y1 = P[p1 + 1], x2 = P[p2], y2 = P[p2 + 1];
            det = (x0 - x2) * (y1 - y2) - (y0 - y2) * (x1 - x2);
        } else if (AXIS == 1) {
            float x0 = P[p0], z0 = P[p0 + 2], x1 = P[p1], z1 = P[p1 + 2], x2 = P[p2], z2 = P[p2 + 2];
            det = (x0 - x1) * (z2 - z1) - (z0 - z1) * (x2 - x1);
        } else {
            float y0 = P[p0 + 1], z0 = P[p0 + 2], y1 = P[p1 + 1], z1 = P[p1 + 2], y2 = P[p2 + 1], z2 = P[p2 + 2];
            det = (y1 - y0) * (z2 - z0) - (z1 - z0) * (y2 - y0);
        }
        float v = det * (1.0f / 6.0f);
        __nv_bfloat16 h = __float2bfloat16_rn(v);
        __nv_bfloat16 l = __float2bfloat16_rn(v - __bfloat162float(h));
        g_dsp[b * N_TRI + t] = h;
        g_dsp[(16 + b) * N_TRI + t] = l;
    }
}

// ------------------------- helpers -------------------------
__device__ __forceinline__ uint32_t smem_u32(const void* p) {
    return (uint32_t)__cvta_generic_to_shared(p);
}
__device__ __forceinline__ void tma2d(uint32_t dst, const CUtensorMap* m, int x, int y, uint32_t mbar) {
    asm volatile(
        "cp.async.bulk.tensor.2d.shared::cta.global.tile.mbarrier::complete_tx::bytes "
        "[%0], [%1, {%2, %3}], [%4];"
        :: "r"(dst), "l"(m), "r"(x), "r"(y), "r"(mbar) : "memory");
}
__device__ __forceinline__ void mbar_wait(uint32_t addr, uint32_t parity) {
    asm volatile(
        "{\n\t.reg .pred P;\n\t"
        "W%=:\n\tmbarrier.try_wait.parity.acquire.cta.shared::cta.b64 P, [%0], %1;\n\t"
        "@!P bra W%=;\n\t}"
        :: "r"(addr), "r"(parity) : "memory");
}
__device__ __forceinline__ uint32_t bhi(float a0, float a1) {
    uint32_t h;
    asm("cvt.rn.bf16x2.f32 %0, %1, %2;" : "=r"(h) : "f"(a1), "f"(a0));
    return h;
}
#define MMA16816(C0,C1,C2,C3,A0,A1,A2,A3,B0,B1) \
    asm("mma.sync.aligned.m16n8k16.row.col.f32.bf16.bf16.f32 " \
        "{%0,%1,%2,%3},{%4,%5,%6,%7},{%8,%9},{%0,%1,%2,%3};" \
        : "+f"(C0), "+f"(C1), "+f"(C2), "+f"(C3) \
        : "r"(A0), "r"(A1), "r"(A2), "r"(A3), "r"(B0), "r"(B1))

// ------------------------- GEMM pass 1: f32 Vf in, writes coalesced bf16 hi-plane -------------------------
__global__ void __launch_bounds__(256) k_gemm1(const __grid_constant__ CUtensorMap tmA,
                                               const __grid_constant__ CUtensorMap tmB) {
    extern __shared__ __align__(1024) char sm[];
    __shared__ __align__(8) unsigned long long s_mbar[NST];

    const int tid  = threadIdx.x;
    const int lane = tid & 31;
    const int w    = tid >> 5;
    const int g    = lane >> 2;
    const int tig  = lane & 3;
    const int mbase = blockIdx.x * 128;
    const int ksid  = blockIdx.y;
    const int c0 = (NCHUNK * ksid) / KS;
    const int c1 = (NCHUNK * (ksid + 1)) / KS;

    uint32_t mb[NST];
#pragma unroll
    for (int s = 0; s < NST; s++) mb[s] = smem_u32(&s_mbar[s]);
    if (tid == 0) {
#pragma unroll
        for (int s = 0; s < NST; s++)
            asm volatile("mbarrier.init.shared.b64 [%0], 1;" :: "r"(mb[s]) : "memory");
        asm volatile("fence.proxy.async.shared::cta;" ::: "memory");
    }
    __syncthreads();

    const uint32_t sbase = smem_u32(sm);

    auto issue = [&](int st, int it) {
        if (tid == 0) {
            const int t0 = it * CK;
            asm volatile("mbarrier.arrive.expect_tx.shared.b64 _, [%0], %1;"
                         :: "r"(mb[st]), "r"((uint32_t)STAGE_TX) : "memory");
            tma2d(sbase + st * STAGE_SZ,           &tmA, t0,      mbase, mb[st]);
            tma2d(sbase + st * STAGE_SZ + A_HALF,  &tmA, t0 + 32, mbase, mb[st]);
            tma2d(sbase + st * STAGE_SZ + A_STAGE, &tmB, t0,      0,     mb[st]);
        }
    };

    const int niter = c1 - c0;
#pragma unroll
    for (int s = 0; s < NST; s++)
        if (s < niter) issue(s, c0 + s);

    float acc[2][4];
#pragma unroll
    for (int nt = 0; nt < 2; nt++)
#pragma unroll
        for (int q = 0; q < 4; q++) acc[nt][q] = 0.f;

    int phase[NST] = { 0, 0, 0 };
    int st = 0;
    const int swz = g << 4;

    const int seg   = tid & 7;
    const int rbase = tid >> 3;
    const int segoff = (seg & 3) * 32;

    for (int li = 0; li < niter; ++li) {
        mbar_wait(mb[st], phase[st]);
        phase[st] ^= 1;

        const char* S = sm + st * STAGE_SZ;
        const char* Brow = S + A_STAGE + g * 128;
        const int tglob = (c0 + li) * CK;

        // coalesced hi-plane store (row-contiguous, STG.128)
        {
            const char* Af = S + (seg >> 2) * A_HALF;
#pragma unroll
            for (int j = 0; j < 4; j++) {
                const int r = rbase + 32 * j;
                const int rswz = (r & 7) << 4;
                const char* p = Af + r * 128;
                float4 f0 = *reinterpret_cast<const float4*>(p + (segoff ^ rswz));
                float4 f1 = *reinterpret_cast<const float4*>(p + ((segoff + 16) ^ rswz));
                uint4 o;
                o.x = bhi(f0.x, f0.y); o.y = bhi(f0.z, f0.w);
                o.z = bhi(f1.x, f1.y); o.w = bhi(f1.z, f1.w);
                *reinterpret_cast<uint4*>(
                    (char*)g_vfh + ((size_t)(mbase + r) * N_TRI + tglob) * 2 + seg * 16) = o;
            }
        }

#pragma unroll
        for (int ks = 0; ks < 4; ks++) {
            const char* Ah = S + (ks >> 1) * A_HALF + (w * 16 + g) * 128;
            const int cb = (ks & 1) * 64 + tig * 8;
            float2 x00 = *reinterpret_cast<const float2*>(Ah + ((cb)      ^ swz));
            float2 x01 = *reinterpret_cast<const float2*>(Ah + ((cb + 32) ^ swz));
            float2 x10 = *reinterpret_cast<const float2*>(Ah + 1024 + ((cb)      ^ swz));
            float2 x11 = *reinterpret_cast<const float2*>(Ah + 1024 + ((cb + 32) ^ swz));
            uint32_t ah0 = bhi(x00.x, x00.y);
            uint32_t ah1 = bhi(x10.x, x10.y);
            uint32_t ah2 = bhi(x01.x, x01.y);
            uint32_t ah3 = bhi(x11.x, x11.y);

            const int kb = ks * 32 + tig * 4;
            uint32_t bh0a = *reinterpret_cast<const uint32_t*>(Brow + ((kb)      ^ swz));
            uint32_t bh0b = *reinterpret_cast<const uint32_t*>(Brow + ((kb + 16) ^ swz));
            uint32_t bh1a = *reinterpret_cast<const uint32_t*>(Brow + 8 * 128  + ((kb)      ^ swz));
            uint32_t bh1b = *reinterpret_cast<const uint32_t*>(Brow + 8 * 128  + ((kb + 16) ^ swz));
            uint32_t bl0a = *reinterpret_cast<const uint32_t*>(Brow + 16 * 128 + ((kb)      ^ swz));
            uint32_t bl0b = *reinterpret_cast<const uint32_t*>(Brow + 16 * 128 + ((kb + 16) ^ swz));
            uint32_t bl1a = *reinterpret_cast<const uint32_t*>(Brow + 24 * 128 + ((kb)      ^ swz));
            uint32_t bl1b = *reinterpret_cast<const uint32_t*>(Brow + 24 * 128 + ((kb + 16) ^ swz));

            MMA16816(acc[0][0], acc[0][1], acc[0][2], acc[0][3], ah0, ah1, ah2, ah3, bh0a, bh0b);
            MMA16816(acc[0][0], acc[0][1], acc[0][2], acc[0][3], ah0, ah1, ah2, ah3, bl0a, bl0b);
            MMA16816(acc[1][0], acc[1][1], acc[1][2], acc[1][3], ah0, ah1, ah2, ah3, bh1a, bh1b);
            MMA16816(acc[1][0], acc[1][1], acc[1][2], acc[1][3], ah0, ah1, ah2, ah3, bl1a, bl1b);
        }

        __syncthreads();
        if (li + NST < niter) issue(st, c0 + li + NST);
        st = (st + 1 == NST) ? 0 : st + 1;
    }

    const int m0 = mbase + w * 16 + g;
    const int m1 = m0 + 8;
#pragma unroll
    for (int nt = 0; nt < 2; nt++) {
        const int n0 = nt * 8 + tig * 2;
        if (m0 < N_MOV)
            *reinterpret_cast<float2*>(&g_cpart[((size_t)ksid * 4096 + m0) * 16 + n0]) =
                make_float2(acc[nt][0], acc[nt][1]);
        if (m1 < N_MOV)
            *reinterpret_cast<float2*>(&g_cpart[((size_t)ksid * 4096 + m1) * 16 + n0]) =
                make_float2(acc[nt][2], acc[nt][3]);
    }
}

// ------------------------- GEMM pass 2/3: bf16 hi-plane, CK2=128, 2-stage -------------------------
__global__ void __launch_bounds__(256) k_gemm2(const __grid_constant__ CUtensorMap tmH,
                                               const __grid_constant__ CUtensorMap tmB) {
    extern __shared__ __align__(1024) char sm[];
    __shared__ __align__(8) unsigned long long s_mbar[NST2];

    const int tid  = threadIdx.x;
    const int lane = tid & 31;
    const int w    = tid >> 5;
    const int g    = lane >> 2;
    const int tig  = lane & 3;
    const int mbase = blockIdx.x * 128;
    const int ksid  = blockIdx.y;
    const int c0 = (NCHUNK2 * ksid) / KS;
    const int c1 = (NCHUNK2 * (ksid + 1)) / KS;

    uint32_t mb[NST2];
#pragma unroll
    for (int s = 0; s < NST2; s++) mb[s] = smem_u32(&s_mbar[s]);
    if (tid == 0) {
#pragma unroll
        for (int s = 0; s < NST2; s++)
            asm volatile("mbarrier.init.shared.b64 [%0], 1;" :: "r"(mb[s]) : "memory");
        asm volatile("fence.proxy.async.shared::cta;" ::: "memory");
    }
    __syncthreads();

    const uint32_t sbase = smem_u32(sm);

    auto issue = [&](int st, int it) {
        if (tid == 0) {
            const int t0 = it * CK2;
            asm volatile("mbarrier.arrive.expect_tx.shared.b64 _, [%0], %1;"
                         :: "r"(mb[st]), "r"((uint32_t)STAGE2_TX) : "memory");
            tma2d(sbase + st * STAGE2_SZ,                       &tmH, t0,      mbase, mb[st]);
            tma2d(sbase + st * STAGE2_SZ + A2_HALF,             &tmH, t0 + 64, mbase, mb[st]);
            tma2d(sbase + st * STAGE2_SZ + A2_STAGE,            &tmB, t0,      0,     mb[st]);
            tma2d(sbase + st * STAGE2_SZ + A2_STAGE + B2_HALF,  &tmB, t0 + 64, 0,     mb[st]);
        }
    };

    const int niter = c1 - c0;
#pragma unroll
    for (int s = 0; s < NST2; s++)
        if (s < niter) issue(s, c0 + s);

    float acc[2][4];
#pragma unroll
    for (int nt = 0; nt < 2; nt++)
#pragma unroll
        for (int q = 0; q < 4; q++) acc[nt][q] = 0.f;

    int phase[NST2] = { 0, 0 };
    int st = 0;
    const int swz = g << 4;

    for (int li = 0; li < niter; ++li) {
        mbar_wait(mb[st], phase[st]);
        phase[st] ^= 1;

        const char* S = sm + st * STAGE2_SZ;

#pragma unroll
        for (int half = 0; half < 2; half++) {
            const char* Arow = S + half * A2_HALF + (w * 16 + g) * 128;
            const char* Brow = S + A2_STAGE + half * B2_HALF + g * 128;
#pragma unroll
            for (int ks = 0; ks < 4; ks++) {
                const int kb = ks * 32 + tig * 4;
                uint32_t ah0 = *reinterpret_cast<const uint32_t*>(Arow + ((kb)      ^ swz));
                uint32_t ah2 = *reinterpret_cast<const uint32_t*>(Arow + ((kb + 16) ^ swz));
                uint32_t ah1 = *reinterpret_cast<const uint32_t*>(Arow + 8 * 128 + ((kb)      ^ swz));
                uint32_t ah3 = *reinterpret_cast<const uint32_t*>(Arow + 8 * 128 + ((kb + 16) ^ swz));

                uint32_t bh0a = *reinterpret_cast<const uint32_t*>(Brow + ((kb)      ^ swz));
                uint32_t bh0b = *reinterpret_cast<const uint32_t*>(Brow + ((kb + 16) ^ swz));
                uint32_t bh1a = *reinterpret_cast<const uint32_t*>(Brow + 8 * 128  + ((kb)      ^ swz));
                uint32_t bh1b = *reinterpret_cast<const uint32_t*>(Brow + 8 * 128  + ((kb + 16) ^ swz));
                uint32_t bl0a = *reinterpret_cast<const uint32_t*>(Brow + 16 * 128 + ((kb)      ^ swz));
                uint32_t bl0b = *reinterpret_cast<const uint32_t*>(Brow + 16 * 128 + ((kb + 16) ^ swz));
                uint32_t bl1a = *reinterpret_cast<const uint32_t*>(Brow + 24 * 128 + ((kb)      ^ swz));
                uint32_t bl1b = *reinterpret_cast<const uint32_t*>(Brow + 24 * 128 + ((kb + 16) ^ swz));

                MMA16816(acc[0][0], acc[0][1], acc[0][2], acc[0][3], ah0, ah1, ah2, ah3, bh0a, bh0b);
                MMA16816(acc[0][0], acc[0][1], acc[0][2], acc[0][3], ah0, ah1, ah2, ah3, bl0a, bl0b);
                MMA16816(acc[1][0], acc[1][1], acc[1][2], acc[1][3], ah0, ah1, ah2, ah3, bh1a, bh1b);
                MMA16816(acc[1][0], acc[1][1], acc[1][2], acc[1][3], ah0, ah1, ah2, ah3, bl1a, bl1b);
            }
        }

        __syncthreads();
        if (li + NST2 < niter) issue(st, c0 + li + NST2);
        st = (st + 1 == NST2) ? 0 : st + 1;
    }

    const int m0 = mbase + w * 16 + g;
    const int m1 = m0 + 8;
#pragma unroll
    for (int nt = 0; nt < 2; nt++) {
        const int n0 = nt * 8 + tig * 2;
        if (m0 < N_MOV)
            *reinterpret_cast<float2*>(&g_cpart[((size_t)ksid * 4096 + m0) * 16 + n0]) =
                make_float2(acc[nt][0], acc[nt][1]);
        if (m1 < N_MOV)
            *reinterpret_cast<float2*>(&g_cpart[((size_t)ksid * 4096 + m1) * 16 + n0]) =
                make_float2(acc[nt][2], acc[nt][3]);
    }
}

// ------------------------- fused: finalize c, vol reduce, scale, update out & pz -------------------------
__global__ void k_scale_update(const int* __restrict__ idx1, const float* __restrict__ x,
                               float* __restrict__ out, int axis) {
    __shared__ float red[256];
    __shared__ double dv[128];
    __shared__ float s_scale;
    int b = blockIdx.x;
    int tid = threadIdx.x;

    if (tid < 128) {
        double v = 0.0;
        if (tid < 64) { if (tid < VOLBLK) v = g_volpart[b * VOLBLK + tid]; }
        else          { if (tid - 64 < VOLBLK) v = g_volpart[BATCH * VOLBLK + (tid - 64)]; }
        dv[tid] = v;
    }

    float sq = 0.f;
    for (int m = tid; m < N_MOV; m += 256) {
        float cv = 0.f;
#pragma unroll
        for (int sp = 0; sp < KS; sp++)
            cv += g_cpart[((size_t)sp * 4096 + m) * 16 + b];
        g_c[b * N_MOV + m] = cv;
        sq += cv * cv;
    }
    red[tid] = sq;
    __syncthreads();
    for (int o = 32; o > 0; o >>= 1) {
        if (tid < o)                   dv[tid] += dv[tid + o];
        if (tid >= 64 && tid < 64 + o) dv[tid] += dv[tid + o];
        __syncthreads();
    }
    for (int o = 128; o > 0; o >>= 1) {
        if (tid < o) red[tid] += red[tid + o];
        __syncthreads();
    }
    if (tid == 0) {
        float a = (float)((dv[64] - dv[0]) / 3.0);
        s_scale = a / (red[0] + EPSF);
    }
    __syncthreads();
    const float s = s_scale;
    for (int m = tid; m < N_MOV; m += 256) {
        int i = b * N_MOV + m;
        float nv = x[i * 3 + axis] + g_c[i] * s;
        out[i * 3 + axis] = nv;
        int p = idx1[m];
        if (g_owner[p] == m) g_pz[((size_t)b * N_PTS + p) * 3 + axis] = nv;
    }
}

// ------------------------- host -------------------------
typedef CUresult (*EncodeFn)(CUtensorMap*, CUtensorMapDataType, cuuint32_t, void*,
                             const cuuint64_t*, const cuuint64_t*, const cuuint32_t*,
                             const cuuint32_t*, CUtensorMapInterleave, CUtensorMapSwizzle,
                             CUtensorMapL2promotion, CUtensorMapFloatOOBfill);

extern "C" void kernel_launch(void* const* d_in, const int* in_sizes, int n_in,
                              void* d_out, int out_size) {
    const float* x   = (const float*)d_in[0];
    const float* y   = (const float*)d_in[1];
    const float* pz0 = (const float*)d_in[2];
    const float* Vf  = (const float*)d_in[3];
    const int* idx1  = (const int*)d_in[4];
    const int* idx2  = (const int*)d_in[5];
    const int* tri   = (const int*)d_in[6];
    float* out = (float*)d_out;

    cudaFuncSetAttribute(k_gemm1, cudaFuncAttributeMaxDynamicSharedMemorySize, SMEM_BYTES);
    cudaFuncSetAttribute(k_gemm2, cudaFuncAttributeMaxDynamicSharedMemorySize, SMEM2_BYTES);

    EncodeFn enc = nullptr;
    {
        void* p = nullptr;
        cudaDriverEntryPointQueryResult qr;
        cudaGetDriverEntryPoint("cuTensorMapEncodeTiled", &p, cudaEnableDefault, &qr);
        enc = (EncodeFn)p;
    }

    void* dsp_ptr = nullptr;
    cudaGetSymbolAddress(&dsp_ptr, g_dsp);
    void* vfh_ptr = nullptr;
    cudaGetSymbolAddress(&vfh_ptr, g_vfh);

    CUtensorMap tmA, tmB, tmH;
    {
        cuuint64_t dims[2]    = { (cuuint64_t)N_TRI, (cuuint64_t)N_MOV };
        cuuint64_t strides[1] = { (cuuint64_t)N_TRI * 4 };
        cuuint32_t box[2]     = { 32, 128 };
        cuuint32_t es[2]      = { 1, 1 };
        enc(&tmA, CU_TENSOR_MAP_DATA_TYPE_FLOAT32, 2, (void*)Vf,
            dims, strides, box, es,
            CU_TENSOR_MAP_INTERLEAVE_NONE, CU_TENSOR_MAP_SWIZZLE_128B,
            CU_TENSOR_MAP_L2_PROMOTION_L2_128B, CU_TENSOR_MAP_FLOAT_OOB_FILL_NONE);
    }
    {
        cuuint64_t dims[2]    = { (cuuint64_t)N_TRI, 32 };
        cuuint64_t strides[1] = { (cuuint64_t)N_TRI * 2 };
        cuuint32_t box[2]     = { 64, 32 };
        cuuint32_t es[2]      = { 1, 1 };
        enc(&tmB, CU_TENSOR_MAP_DATA_TYPE_BFLOAT16, 2, dsp_ptr,
            dims, strides, box, es,
            CU_TENSOR_MAP_INTERLEAVE_NONE, CU_TENSOR_MAP_SWIZZLE_128B,
            CU_TENSOR_MAP_L2_PROMOTION_L2_128B, CU_TENSOR_MAP_FLOAT_OOB_FILL_NONE);
    }
    {
        cuuint64_t dims[2]    = { (cuuint64_t)N_TRI, 4096 };
        cuuint64_t strides[1] = { (cuuint64_t)N_TRI * 2 };
        cuuint32_t box[2]     = { 64, 128 };
        cuuint32_t es[2]      = { 1, 1 };
        enc(&tmH, CU_TENSOR_MAP_DATA_TYPE_BFLOAT16, 2, vfh_ptr,
            dims, strides, box, es,
            CU_TENSOR_MAP_INTERLEAVE_NONE, CU_TENSOR_MAP_SWIZZLE_128B,
            CU_TENSOR_MAP_L2_PROMOTION_L2_128B, CU_TENSOR_MAP_FLOAT_OOB_FILL_NONE);
    }

    static cudaStream_t s2 = nullptr;
    static cudaEvent_t evA = nullptr, evB = nullptr;
    if (!s2) {
        cudaStreamCreateWithFlags(&s2, cudaStreamNonBlocking);
        cudaEventCreateWithFlags(&evA, cudaEventDisableTiming);
        cudaEventCreateWithFlags(&evB, cudaEventDisableTiming);
    }

    void* op = nullptr;
    cudaGetSymbolAddress(&op, g_owner);
    cudaMemsetAsync(op, 0xFF, 2 * N_PTS * sizeof(int));

    k_owners<<<16, 256>>>(idx1, idx2);
    k_build<<<375, 256>>>(x, y, pz0);

    // fork: k_vol depends only on k_build; runs concurrent with det2/gemm1
    cudaEventRecord(evA, 0);
    cudaStreamWaitEvent(s2, evA, 0);
    k_vol<<<dim3(VOLBLK, BATCH + 1), 256, 0, s2>>>(pz0, tri);
    cudaEventRecord(evB, s2);

    k_det<2><<<dim3(63, 8), 256>>>(tri);
    k_gemm1<<<dim3(MTILES, KS), 256, SMEM_BYTES>>>(tmA, tmB);
    cudaStreamWaitEvent(0, evB, 0);
    k_scale_update<<<BATCH, 256>>>(idx1, x, out, 2);

    k_det<1><<<dim3(63, 8), 256>>>(tri);
    k_gemm2<<<dim3(MTILES, KS), 256, SMEM2_BYTES>>>(tmH, tmB);
    k_scale_update<<<BATCH, 256>>>(idx1, x, out, 1);

    k_det<0><<<dim3(63, 8), 256>>>(tri);
    k_gemm2<<<dim3(MTILES, KS), 256, SMEM2_BYTES>>>(tmH, tmB);
    k_scale_update<<<BATCH, 256>>>(idx1, x, out, 0);
}

// round 17
// speedup vs baseline: 1.2927x; 1.0086x over previous
#include <cuda_runtime.h>
#include <cuda.h>
#include <cuda_bf16.h>
#include <cstdint>

#define N_PTS 6000
#define N_TRI 16000
#define N_MOV 4000
#define N_BND 1500
#define BATCH 16
#define EPSF 1e-8f

// GEMM: C[m=4000,n=16] = Vf[m,k=16000] * D[k,16]
#define CK 64
#define NCHUNK (N_TRI / CK)    // 250
#define KS 9
#define MTILES 32
#define NST 3                  // pass-1 stages (f32 A)

#define A_HALF 16384
#define A_STAGE (2 * A_HALF)                 // 32768
#define B_STAGE 4096
#define STAGE_SZ (A_STAGE + B_STAGE)         // 36864
#define SMEM_BYTES (NST * STAGE_SZ)          // 110592 -> 2 CTAs/SM (measured)
#define STAGE_TX STAGE_SZ

// pass-2/3: bf16 A plane, CK2=128, 2-stage
#define CK2 128
#define NCHUNK2 (N_TRI / CK2)                // 125
#define A2_HALF 16384
#define A2_STAGE (2 * A2_HALF)               // 32768
#define B2_HALF 4096
#define B2_STAGE (2 * B2_HALF)               // 8192
#define STAGE2_SZ (A2_STAGE + B2_STAGE)      // 40960
#define NST2 2
#define SMEM2_BYTES (NST2 * STAGE2_SZ)       // 81920 -> 2 CTAs/SM
#define STAGE2_TX STAGE2_SZ

#define VOLBLK 63

// ------------------------- device scratch -------------------------
__device__ int    g_owner[2 * N_PTS];
__device__ double g_volpart[(BATCH + 1) * VOLBLK];
__device__ __align__(16) float4 g_pz4[BATCH * N_PTS];        // xyz + pad (LDG.128 gathers)
__device__ __align__(256) __nv_bfloat16 g_dsp[32 * N_TRI];   // rows 0-15 hi[b], 16-31 lo[b]
__device__ __align__(256) __nv_bfloat16 g_vfh[(size_t)4096 * N_TRI];  // Vf hi-plane
__device__ float  g_cpart[KS * 4096 * 16];
__device__ float  g_c[BATCH * N_MOV];

// ------------------------- small kernels -------------------------
__global__ void k_owners(const int* __restrict__ idx1, const int* __restrict__ idx2) {
    int i = blockIdx.x * 256 + threadIdx.x;
    if (i < N_MOV) atomicMax(&g_owner[idx1[i]], i);
    if (i < N_BND) atomicMax(&g_owner[N_PTS + idx2[i]], i);
}

__global__ void k_build(const float* __restrict__ x, const float* __restrict__ y,
                        const float* __restrict__ pz0) {
    int i = blockIdx.x * 256 + threadIdx.x;
    if (i >= BATCH * N_PTS) return;
    int b = i / N_PTS, p = i - b * N_PTS;
    float cx = pz0[p * 3 + 0], cy = pz0[p * 3 + 1], cz = pz0[p * 3 + 2];
    int o2 = g_owner[N_PTS + p];
    if (o2 >= 0) {
        cx = y[b * (2 * N_BND) + o2 * 2 + 0];
        cz = y[b * (2 * N_BND) + o2 * 2 + 1];
    }
    int o1 = g_owner[p];
    if (o1 >= 0) {
        cx = x[(b * N_MOV + o1) * 3 + 0];
        cy = x[(b * N_MOV + o1) * 3 + 1];
        cz = x[(b * N_MOV + o1) * 3 + 2];
    }
    g_pz4[i] = make_float4(cx, cy, cz, 0.f);
}

__global__ void k_vol(const float* __restrict__ pz0, const int* __restrict__ tri) {
    __shared__ double sred[256];
    int t = blockIdx.x * 256 + threadIdx.x;
    int b = blockIdx.y;
    double contrib = 0.0;
    if (t < N_TRI) {
        int p0 = tri[3 * t + 0], p1 = tri[3 * t + 1], p2 = tri[3 * t + 2];
        float x0, y0, z0, x1, y1, z1, x2, y2, z2;
        if (b < BATCH) {
            const float4* P = g_pz4 + (size_t)b * N_PTS;
            float4 v0 = P[p0], v1 = P[p1], v2 = P[p2];
            x0 = v0.x; y0 = v0.y; z0 = v0.z;
            x1 = v1.x; y1 = v1.y; z1 = v1.z;
            x2 = v2.x; y2 = v2.y; z2 = v2.z;
        } else {
            x0 = pz0[p0 * 3]; y0 = pz0[p0 * 3 + 1]; z0 = pz0[p0 * 3 + 2];
            x1 = pz0[p1 * 3]; y1 = pz0[p1 * 3 + 1]; z1 = pz0[p1 * 3 + 2];
            x2 = pz0[p2 * 3]; y2 = pz0[p2 * 3 + 1]; z2 = pz0[p2 * 3 + 2];
        }
        float det = (y1 - y0) * (z2 - z0) - (z1 - z0) * (y2 - y0);
        contrib = (double)((x0 + x1 + x2) * (det * (1.0f / 6.0f)));
    }
    sred[threadIdx.x] = contrib;
    __syncthreads();
    for (int o = 128; o > 0; o >>= 1) {
        if (threadIdx.x < o) sred[threadIdx.x] += sred[threadIdx.x + o];
        __syncthreads();
    }
    if (threadIdx.x == 0) g_volpart[b * VOLBLK + blockIdx.x] = sred[0];
}

// dets -> bf16 hi/lo planes; grid (63, 8), 2 batches/thread, LDG.128 vertex gathers
template <int AXIS>
__global__ void k_det(const int* __restrict__ tri) {
    int t = blockIdx.x * 256 + threadIdx.x;
    if (t >= N_TRI) return;
    const int p0 = tri[3 * t + 0], p1 = tri[3 * t + 1], p2 = tri[3 * t + 2];
    const int b0 = blockIdx.y * 2;
#pragma unroll
    for (int bi = 0; bi < 2; bi++) {
        const int b = b0 + bi;
        const float4* P = g_pz4 + (size_t)b * N_PTS;
        float4 v0 = P[p0], v1 = P[p1], v2 = P[p2];
        float det;
        if (AXIS == 2) {        // (x,y), pivot vertex 2
            det = (v0.x - v2.x) * (v1.y - v2.y) - (v0.y - v2.y) * (v1.x - v2.x);
        } else if (AXIS == 1) { // (x,z), pivot vertex 1
            det = (v0.x - v1.x) * (v2.z - v1.z) - (v0.z - v1.z) * (v2.x - v1.x);
        } else {                // (y,z), pivot vertex 0
            det = (v1.y - v0.y) * (v2.z - v0.z) - (v1.z - v0.z) * (v2.y - v0.y);
        }
        float v = det * (1.0f / 6.0f);
        __nv_bfloat16 h = __float2bfloat16_rn(v);
        __nv_bfloat16 l = __float2bfloat16_rn(v - __bfloat162float(h));
        g_dsp[b * N_TRI + t] = h;
        g_dsp[(16 + b) * N_TRI + t] = l;
    }
}

// ------------------------- helpers -------------------------
__device__ __forceinline__ uint32_t smem_u32(const void* p) {
    return (uint32_t)__cvta_generic_to_shared(p);
}
__device__ __forceinline__ void tma2d(uint32_t dst, const CUtensorMap* m, int x, int y, uint32_t mbar) {
    asm volatile(
        "cp.async.bulk.tensor.2d.shared::cta.global.tile.mbarrier::complete_tx::bytes "
        "[%0], [%1, {%2, %3}], [%4];"
        :: "r"(dst), "l"(m), "r"(x), "r"(y), "r"(mbar) : "memory");
}
__device__ __forceinline__ void mbar_wait(uint32_t addr, uint32_t parity) {
    asm volatile(
        "{\n\t.reg .pred P;\n\t"
        "W%=:\n\tmbarrier.try_wait.parity.acquire.cta.shared::cta.b64 P, [%0], %1;\n\t"
        "@!P bra W%=;\n\t}"
        :: "r"(addr), "r"(parity) : "memory");
}
__device__ __forceinline__ uint32_t bhi(float a0, float a1) {
    uint32_t h;
    asm("cvt.rn.bf16x2.f32 %0, %1, %2;" : "=r"(h) : "f"(a1), "f"(a0));
    return h;
}
#define MMA16816(C0,C1,C2,C3,A0,A1,A2,A3,B0,B1) \
    asm("mma.sync.aligned.m16n8k16.row.col.f32.bf16.bf16.f32 " \
        "{%0,%1,%2,%3},{%4,%5,%6,%7},{%8,%9},{%0,%1,%2,%3};" \
        : "+f"(C0), "+f"(C1), "+f"(C2), "+f"(C3) \
        : "r"(A0), "r"(A1), "r"(A2), "r"(A3), "r"(B0), "r"(B1))

// ------------------------- GEMM pass 1: f32 Vf in, writes coalesced bf16 hi-plane -------------------------
__global__ void __launch_bounds__(256) k_gemm1(const __grid_constant__ CUtensorMap tmA,
                                               const __grid_constant__ CUtensorMap tmB) {
    extern __shared__ __align__(1024) char sm[];
    __shared__ __align__(8) unsigned long long s_mbar[NST];

    const int tid  = threadIdx.x;
    const int lane = tid & 31;
    const int w    = tid >> 5;
    const int g    = lane >> 2;
    const int tig  = lane & 3;
    const int mbase = blockIdx.x * 128;
    const int ksid  = blockIdx.y;
    const int c0 = (NCHUNK * ksid) / KS;
    const int c1 = (NCHUNK * (ksid + 1)) / KS;

    uint32_t mb[NST];
#pragma unroll
    for (int s = 0; s < NST; s++) mb[s] = smem_u32(&s_mbar[s]);
    if (tid == 0) {
#pragma unroll
        for (int s = 0; s < NST; s++)
            asm volatile("mbarrier.init.shared.b64 [%0], 1;" :: "r"(mb[s]) : "memory");
        asm volatile("fence.proxy.async.shared::cta;" ::: "memory");
    }
    __syncthreads();

    const uint32_t sbase = smem_u32(sm);

    auto issue = [&](int st, int it) {
        if (tid == 0) {
            const int t0 = it * CK;
            asm volatile("mbarrier.arrive.expect_tx.shared.b64 _, [%0], %1;"
                         :: "r"(mb[st]), "r"((uint32_t)STAGE_TX) : "memory");
            tma2d(sbase + st * STAGE_SZ,           &tmA, t0,      mbase, mb[st]);
            tma2d(sbase + st * STAGE_SZ + A_HALF,  &tmA, t0 + 32, mbase, mb[st]);
            tma2d(sbase + st * STAGE_SZ + A_STAGE, &tmB, t0,      0,     mb[st]);
        }
    };

    const int niter = c1 - c0;
#pragma unroll
    for (int s = 0; s < NST; s++)
        if (s < niter) issue(s, c0 + s);

    float acc[2][4];
#pragma unroll
    for (int nt = 0; nt < 2; nt++)
#pragma unroll
        for (int q = 0; q < 4; q++) acc[nt][q] = 0.f;

    int phase[NST] = { 0, 0, 0 };
    int st = 0;
    const int swz = g << 4;

    const int seg   = tid & 7;
    const int rbase = tid >> 3;
    const int segoff = (seg & 3) * 32;

    for (int li = 0; li < niter; ++li) {
        mbar_wait(mb[st], phase[st]);
        phase[st] ^= 1;

        const char* S = sm + st * STAGE_SZ;
        const char* Brow = S + A_STAGE + g * 128;
        const int tglob = (c0 + li) * CK;

        // coalesced hi-plane store (row-contiguous, STG.128)
        {
            const char* Af = S + (seg >> 2) * A_HALF;
#pragma unroll
            for (int j = 0; j < 4; j++) {
                const int r = rbase + 32 * j;
                const int rswz = (r & 7) << 4;
                const char* p = Af + r * 128;
                float4 f0 = *reinterpret_cast<const float4*>(p + (segoff ^ rswz));
                float4 f1 = *reinterpret_cast<const float4*>(p + ((segoff + 16) ^ rswz));
                uint4 o;
                o.x = bhi(f0.x, f0.y); o.y = bhi(f0.z, f0.w);
                o.z = bhi(f1.x, f1.y); o.w = bhi(f1.z, f1.w);
                *reinterpret_cast<uint4*>(
                    (char*)g_vfh + ((size_t)(mbase + r) * N_TRI + tglob) * 2 + seg * 16) = o;
            }
        }

#pragma unroll
        for (int ks = 0; ks < 4; ks++) {
            const char* Ah = S + (ks >> 1) * A_HALF + (w * 16 + g) * 128;
            const int cb = (ks & 1) * 64 + tig * 8;
            float2 x00 = *reinterpret_cast<const float2*>(Ah + ((cb)      ^ swz));
            float2 x01 = *reinterpret_cast<const float2*>(Ah + ((cb + 32) ^ swz));
            float2 x10 = *reinterpret_cast<const float2*>(Ah + 1024 + ((cb)      ^ swz));
            float2 x11 = *reinterpret_cast<const float2*>(Ah + 1024 + ((cb + 32) ^ swz));
            uint32_t ah0 = bhi(x00.x, x00.y);
            uint32_t ah1 = bhi(x10.x, x10.y);
            uint32_t ah2 = bhi(x01.x, x01.y);
            uint32_t ah3 = bhi(x11.x, x11.y);

            const int kb = ks * 32 + tig * 4;
            uint32_t bh0a = *reinterpret_cast<const uint32_t*>(Brow + ((kb)      ^ swz));
            uint32_t bh0b = *reinterpret_cast<const uint32_t*>(Brow + ((kb + 16) ^ swz));
            uint32_t bh1a = *reinterpret_cast<const uint32_t*>(Brow + 8 * 128  + ((kb)      ^ swz));
            uint32_t bh1b = *reinterpret_cast<const uint32_t*>(Brow + 8 * 128  + ((kb + 16) ^ swz));
            uint32_t bl0a = *reinterpret_cast<const uint32_t*>(Brow + 16 * 128 + ((kb)      ^ swz));
            uint32_t bl0b = *reinterpret_cast<const uint32_t*>(Brow + 16 * 128 + ((kb + 16) ^ swz));
            uint32_t bl1a = *reinterpret_cast<const uint32_t*>(Brow + 24 * 128 + ((kb)      ^ swz));
            uint32_t bl1b = *reinterpret_cast<const uint32_t*>(Brow + 24 * 128 + ((kb + 16) ^ swz));

            MMA16816(acc[0][0], acc[0][1], acc[0][2], acc[0][3], ah0, ah1, ah2, ah3, bh0a, bh0b);
            MMA16816(acc[0][0], acc[0][1], acc[0][2], acc[0][3], ah0, ah1, ah2, ah3, bl0a, bl0b);
            MMA16816(acc[1][0], acc[1][1], acc[1][2], acc[1][3], ah0, ah1, ah2, ah3, bh1a, bh1b);
            MMA16816(acc[1][0], acc[1][1], acc[1][2], acc[1][3], ah0, ah1, ah2, ah3, bl1a, bl1b);
        }

        __syncthreads();
        if (li + NST < niter) issue(st, c0 + li + NST);
        st = (st + 1 == NST) ? 0 : st + 1;
    }

    const int m0 = mbase + w * 16 + g;
    const int m1 = m0 + 8;
#pragma unroll
    for (int nt = 0; nt < 2; nt++) {
        const int n0 = nt * 8 + tig * 2;
        if (m0 < N_MOV)
            *reinterpret_cast<float2*>(&g_cpart[((size_t)ksid * 4096 + m0) * 16 + n0]) =
                make_float2(acc[nt][0], acc[nt][1]);
        if (m1 < N_MOV)
            *reinterpret_cast<float2*>(&g_cpart[((size_t)ksid * 4096 + m1) * 16 + n0]) =
                make_float2(acc[nt][2], acc[nt][3]);
    }
}

// ------------------------- GEMM pass 2/3: bf16 hi-plane, CK2=128, 2-stage -------------------------
__global__ void __launch_bounds__(256) k_gemm2(const __grid_constant__ CUtensorMap tmH,
                                               const __grid_constant__ CUtensorMap tmB) {
    extern __shared__ __align__(1024) char sm[];
    __shared__ __align__(8) unsigned long long s_mbar[NST2];

    const int tid  = threadIdx.x;
    const int lane = tid & 31;
    const int w    = tid >> 5;
    const int g    = lane >> 2;
    const int tig  = lane & 3;
    const int mbase = blockIdx.x * 128;
    const int ksid  = blockIdx.y;
    const int c0 = (NCHUNK2 * ksid) / KS;
    const int c1 = (NCHUNK2 * (ksid + 1)) / KS;

    uint32_t mb[NST2];
#pragma unroll
    for (int s = 0; s < NST2; s++) mb[s] = smem_u32(&s_mbar[s]);
    if (tid == 0) {
#pragma unroll
        for (int s = 0; s < NST2; s++)
            asm volatile("mbarrier.init.shared.b64 [%0], 1;" :: "r"(mb[s]) : "memory");
        asm volatile("fence.proxy.async.shared::cta;" ::: "memory");
    }
    __syncthreads();

    const uint32_t sbase = smem_u32(sm);

    auto issue = [&](int st, int it) {
        if (tid == 0) {
            const int t0 = it * CK2;
            asm volatile("mbarrier.arrive.expect_tx.shared.b64 _, [%0], %1;"
                         :: "r"(mb[st]), "r"((uint32_t)STAGE2_TX) : "memory");
            tma2d(sbase + st * STAGE2_SZ,                       &tmH, t0,      mbase, mb[st]);
            tma2d(sbase + st * STAGE2_SZ + A2_HALF,             &tmH, t0 + 64, mbase, mb[st]);
            tma2d(sbase + st * STAGE2_SZ + A2_STAGE,            &tmB, t0,      0,     mb[st]);
            tma2d(sbase + st * STAGE2_SZ + A2_STAGE + B2_HALF,  &tmB, t0 + 64, 0,     mb[st]);
        }
    };

    const int niter = c1 - c0;
#pragma unroll
    for (int s = 0; s < NST2; s++)
        if (s < niter) issue(s, c0 + s);

    float acc[2][4];
#pragma unroll
    for (int nt = 0; nt < 2; nt++)
#pragma unroll
        for (int q = 0; q < 4; q++) acc[nt][q] = 0.f;

    int phase[NST2] = { 0, 0 };
    int st = 0;
    const int swz = g << 4;

    for (int li = 0; li < niter; ++li) {
        mbar_wait(mb[st], phase[st]);
        phase[st] ^= 1;

        const char* S = sm + st * STAGE2_SZ;

#pragma unroll
        for (int half = 0; half < 2; half++) {
            const char* Arow = S + half * A2_HALF + (w * 16 + g) * 128;
            const char* Brow = S + A2_STAGE + half * B2_HALF + g * 128;
#pragma unroll
            for (int ks = 0; ks < 4; ks++) {
                const int kb = ks * 32 + tig * 4;
                uint32_t ah0 = *reinterpret_cast<const uint32_t*>(Arow + ((kb)      ^ swz));
                uint32_t ah2 = *reinterpret_cast<const uint32_t*>(Arow + ((kb + 16) ^ swz));
                uint32_t ah1 = *reinterpret_cast<const uint32_t*>(Arow + 8 * 128 + ((kb)      ^ swz));
                uint32_t ah3 = *reinterpret_cast<const uint32_t*>(Arow + 8 * 128 + ((kb + 16) ^ swz));

                uint32_t bh0a = *reinterpret_cast<const uint32_t*>(Brow + ((kb)      ^ swz));
                uint32_t bh0b = *reinterpret_cast<const uint32_t*>(Brow + ((kb + 16) ^ swz));
                uint32_t bh1a = *reinterpret_cast<const uint32_t*>(Brow + 8 * 128  + ((kb)      ^ swz));
                uint32_t bh1b = *reinterpret_cast<const uint32_t*>(Brow + 8 * 128  + ((kb + 16) ^ swz));
                uint32_t bl0a = *reinterpret_cast<const uint32_t*>(Brow + 16 * 128 + ((kb)      ^ swz));
                uint32_t bl0b = *reinterpret_cast<const uint32_t*>(Brow + 16 * 128 + ((kb + 16) ^ swz));
                uint32_t bl1a = *reinterpret_cast<const uint32_t*>(Brow + 24 * 128 + ((kb)      ^ swz));
                uint32_t bl1b = *reinterpret_cast<const uint32_t*>(Brow + 24 * 128 + ((kb + 16) ^ swz));

                MMA16816(acc[0][0], acc[0][1], acc[0][2], acc[0][3], ah0, ah1, ah2, ah3, bh0a, bh0b);
                MMA16816(acc[0][0], acc[0][1], acc[0][2], acc[0][3], ah0, ah1, ah2, ah3, bl0a, bl0b);
                MMA16816(acc[1][0], acc[1][1], acc[1][2], acc[1][3], ah0, ah1, ah2, ah3, bh1a, bh1b);
                MMA16816(acc[1][0], acc[1][1], acc[1][2], acc[1][3], ah0, ah1, ah2, ah3, bl1a, bl1b);
            }
        }

        __syncthreads();
        if (li + NST2 < niter) issue(st, c0 + li + NST2);
        st = (st + 1 == NST2) ? 0 : st + 1;
    }

    const int m0 = mbase + w * 16 + g;
    const int m1 = m0 + 8;
#pragma unroll
    for (int nt = 0; nt < 2; nt++) {
        const int n0 = nt * 8 + tig * 2;
        if (m0 < N_MOV)
            *reinterpret_cast<float2*>(&g_cpart[((size_t)ksid * 4096 + m0) * 16 + n0]) =
                make_float2(acc[nt][0], acc[nt][1]);
        if (m1 < N_MOV)
            *reinterpret_cast<float2*>(&g_cpart[((size_t)ksid * 4096 + m1) * 16 + n0]) =
                make_float2(acc[nt][2], acc[nt][3]);
    }
}

// ------------------------- fused: finalize c, vol reduce, scale, update out & pz -------------------------
__global__ void k_scale_update(const int* __restrict__ idx1, const float* __restrict__ x,
                               float* __restrict__ out, int axis) {
    __shared__ float red[256];
    __shared__ double dv[128];
    __shared__ float s_scale;
    int b = blockIdx.x;
    int tid = threadIdx.x;

    if (tid < 128) {
        double v = 0.0;
        if (tid < 64) { if (tid < VOLBLK) v = g_volpart[b * VOLBLK + tid]; }
        else          { if (tid - 64 < VOLBLK) v = g_volpart[BATCH * VOLBLK + (tid - 64)]; }
        dv[tid] = v;
    }

    float sq = 0.f;
    for (int m = tid; m < N_MOV; m += 256) {
        float cv = 0.f;
#pragma unroll
        for (int sp = 0; sp < KS; sp++)
            cv += g_cpart[((size_t)sp * 4096 + m) * 16 + b];
        g_c[b * N_MOV + m] = cv;
        sq += cv * cv;
    }
    red[tid] = sq;
    __syncthreads();
    for (int o = 32; o > 0; o >>= 1) {
        if (tid < o)                   dv[tid] += dv[tid + o];
        if (tid >= 64 && tid < 64 + o) dv[tid] += dv[tid + o];
        __syncthreads();
    }
    for (int o = 128; o > 0; o >>= 1) {
        if (tid < o) red[tid] += red[tid + o];
        __syncthreads();
    }
    if (tid == 0) {
        float a = (float)((dv[64] - dv[0]) / 3.0);
        s_scale = a / (red[0] + EPSF);
    }
    __syncthreads();
    const float s = s_scale;
    for (int m = tid; m < N_MOV; m += 256) {
        int i = b * N_MOV + m;
        float nv = x[i * 3 + axis] + g_c[i] * s;
        out[i * 3 + axis] = nv;
        int p = idx1[m];
        if (g_owner[p] == m)
            (&g_pz4[(size_t)b * N_PTS + p].x)[axis] = nv;
    }
}

// ------------------------- host -------------------------
typedef CUresult (*EncodeFn)(CUtensorMap*, CUtensorMapDataType, cuuint32_t, void*,
                             const cuuint64_t*, const cuuint64_t*, const cuuint32_t*,
                             const cuuint32_t*, CUtensorMapInterleave, CUtensorMapSwizzle,
                             CUtensorMapL2promotion, CUtensorMapFloatOOBfill);

extern "C" void kernel_launch(void* const* d_in, const int* in_sizes, int n_in,
                              void* d_out, int out_size) {
    const float* x   = (const float*)d_in[0];
    const float* y   = (const float*)d_in[1];
    const float* pz0 = (const float*)d_in[2];
    const float* Vf  = (const float*)d_in[3];
    const int* idx1  = (const int*)d_in[4];
    const int* idx2  = (const int*)d_in[5];
    const int* tri   = (const int*)d_in[6];
    float* out = (float*)d_out;

    cudaFuncSetAttribute(k_gemm1, cudaFuncAttributeMaxDynamicSharedMemorySize, SMEM_BYTES);
    cudaFuncSetAttribute(k_gemm2, cudaFuncAttributeMaxDynamicSharedMemorySize, SMEM2_BYTES);

    EncodeFn enc = nullptr;
    {
        void* p = nullptr;
        cudaDriverEntryPointQueryResult qr;
        cudaGetDriverEntryPoint("cuTensorMapEncodeTiled", &p, cudaEnableDefault, &qr);
        enc = (EncodeFn)p;
    }

    void* dsp_ptr = nullptr;
    cudaGetSymbolAddress(&dsp_ptr, g_dsp);
    void* vfh_ptr = nullptr;
    cudaGetSymbolAddress(&vfh_ptr, g_vfh);

    CUtensorMap tmA, tmB, tmH;
    {
        cuuint64_t dims[2]    = { (cuuint64_t)N_TRI, (cuuint64_t)N_MOV };
        cuuint64_t strides[1] = { (cuuint64_t)N_TRI * 4 };
        cuuint32_t box[2]     = { 32, 128 };
        cuuint32_t es[2]      = { 1, 1 };
        enc(&tmA, CU_TENSOR_MAP_DATA_TYPE_FLOAT32, 2, (void*)Vf,
            dims, strides, box, es,
            CU_TENSOR_MAP_INTERLEAVE_NONE, CU_TENSOR_MAP_SWIZZLE_128B,
            CU_TENSOR_MAP_L2_PROMOTION_L2_128B, CU_TENSOR_MAP_FLOAT_OOB_FILL_NONE);
    }
    {
        cuuint64_t dims[2]    = { (cuuint64_t)N_TRI, 32 };
        cuuint64_t strides[1] = { (cuuint64_t)N_TRI * 2 };
        cuuint32_t box[2]     = { 64, 32 };
        cuuint32_t es[2]      = { 1, 1 };
        enc(&tmB, CU_TENSOR_MAP_DATA_TYPE_BFLOAT16, 2, dsp_ptr,
            dims, strides, box, es,
            CU_TENSOR_MAP_INTERLEAVE_NONE, CU_TENSOR_MAP_SWIZZLE_128B,
            CU_TENSOR_MAP_L2_PROMOTION_L2_128B, CU_TENSOR_MAP_FLOAT_OOB_FILL_NONE);
    }
    {
        cuuint64_t dims[2]    = { (cuuint64_t)N_TRI, 4096 };
        cuuint64_t strides[1] = { (cuuint64_t)N_TRI * 2 };
        cuuint32_t box[2]     = { 64, 128 };
        cuuint32_t es[2]      = { 1, 1 };
        enc(&tmH, CU_TENSOR_MAP_DATA_TYPE_BFLOAT16, 2, vfh_ptr,
            dims, strides, box, es,
            CU_TENSOR_MAP_INTERLEAVE_NONE, CU_TENSOR_MAP_SWIZZLE_128B,
            CU_TENSOR_MAP_L2_PROMOTION_L2_128B, CU_TENSOR_MAP_FLOAT_OOB_FILL_NONE);
    }

    static cudaStream_t s2 = nullptr;
    static cudaEvent_t evA = nullptr, evB = nullptr;
    if (!s2) {
        cudaStreamCreateWithFlags(&s2, cudaStreamNonBlocking);
        cudaEventCreateWithFlags(&evA, cudaEventDisableTiming);
        cudaEventCreateWithFlags(&evB, cudaEventDisableTiming);
    }

    void* op = nullptr;
    cudaGetSymbolAddress(&op, g_owner);
    cudaMemsetAsync(op, 0xFF, 2 * N_PTS * sizeof(int));

    k_owners<<<16, 256>>>(idx1, idx2);
    k_build<<<375, 256>>>(x, y, pz0);

    // fork: k_vol depends only on k_build; runs concurrent with det2/gemm1
    cudaEventRecord(evA, 0);
    cudaStreamWaitEvent(s2, evA, 0);
    k_vol<<<dim3(VOLBLK, BATCH + 1), 256, 0, s2>>>(pz0, tri);
    cudaEventRecord(evB, s2);

    k_det<2><<<dim3(63, 8), 256>>>(tri);
    k_gemm1<<<dim3(MTILES, KS), 256, SMEM_BYTES>>>(tmA, tmB);
    cudaStreamWaitEvent(0, evB, 0);
    k_scale_update<<<BATCH, 256>>>(idx1, x, out, 2);

    k_det<1><<<dim3(63, 8), 256>>>(tri);
    k_gemm2<<<dim3(MTILES, KS), 256, SMEM2_BYTES>>>(tmH, tmB);
    k_scale_update<<<BATCH, 256>>>(idx1, x, out, 1);

    k_det<0><<<dim3(63, 8), 256>>>(tri);
    k_gemm2<<<dim3(MTILES, KS), 256, SMEM2_BYTES>>>(tmH, tmB);
    k_scale_update<<<BATCH, 256>>>(idx1, x, out, 0);
}